// round 1
// baseline (speedup 1.0000x reference)
#include <cuda_runtime.h>
#include <cstdint>

#define HB   4
#define CIN  256
#define HID  16
#define IMGH 192
#define IMGW 192
#define HW   (IMGH*IMGW)        // 36864
#define COUT 128
#define CCAT 288

// ---------------- scratch (device globals; no allocation) ----------------
__device__ float g_h[2][HB*HID*HW];        // h0, h1
__device__ float g_cat[HB*CCAT*HW];        // branch outputs concatenated
__device__ float g_w2p[CIN*16*12];         // 3x3 weights repacked [ci][o][t(pad12)]

__constant__ int c_dy[9] = {-1,-1,-1, 0, 1, 1, 1, 0, 0};
__constant__ int c_dx[9] = {-1, 0, 1, 1, 1, 0,-1,-1, 0};

// ---------------- prep: repack 3x3 weights ----------------
__global__ void k_prep(const float* __restrict__ w)
{
    int idx = blockIdx.x*256 + threadIdx.x;      // 0 .. 256*16*12
    if (idx >= CIN*16*12) return;
    int t  = idx % 12;
    int o  = (idx/12) % 16;
    int ci = idx / 192;
    float v = 0.f;
    if (t < 9) v = w[(o*CIN + ci)*9 + t];        // in_w1[o][ci][ky][kx]
    g_w2p[idx] = v;
}

// ---------------- K1: 1x1 conv 256->16 (+bias) -> g_h[0] ----------------
__global__ void k_conv1x1(const float* __restrict__ cen,
                          const float* __restrict__ w,
                          const float* __restrict__ bias)
{
    __shared__ float ws[CIN*16];                 // ws[i][o]
    int tid = threadIdx.x;
    for (int j = tid; j < CIN*16; j += 256) {
        int o = j >> 8, i = j & 255;
        ws[i*16 + o] = w[j];
    }
    __syncthreads();

    int gid = blockIdx.x*256 + tid;
    int bb = gid / HW, p = gid % HW;
    const float* cp = cen + (size_t)bb*CIN*HW + p;

    float acc[16];
    #pragma unroll
    for (int o = 0; o < 16; o++) acc[o] = bias[o];

    for (int i = 0; i < CIN; i++) {
        float v = __ldg(&cp[(size_t)i*HW]);
        const float4* wr = (const float4*)&ws[i*16];
        #pragma unroll
        for (int o4 = 0; o4 < 4; o4++) {
            float4 wv = wr[o4];
            acc[o4*4+0] += v*wv.x;
            acc[o4*4+1] += v*wv.y;
            acc[o4*4+2] += v*wv.z;
            acc[o4*4+3] += v*wv.w;
        }
    }
    float* hp = g_h[0] + (size_t)bb*HID*HW + p;
    #pragma unroll
    for (int o = 0; o < 16; o++) hp[(size_t)o*HW] = acc[o];
}

// ---------------- K2: 3x3 conv 256->16 (+bias), SAME pad -> g_h[1] ------
// block (32,8); tile 64x8 pixels; each thread computes 2 x-adjacent pixels.
__global__ void k_conv3x3(const float* __restrict__ cen,
                          const float* __restrict__ bias)
{
    __shared__ float tile[10][68];               // (8+2) x (64+2) pad->68
    __shared__ float wch[16][12];
    int tx = threadIdx.x, ty = threadIdx.y;
    int tid = ty*32 + tx;
    int x0 = blockIdx.x*64 - 1;
    int y0 = blockIdx.y*8  - 1;
    int bz = blockIdx.z;

    float acc0[16], acc1[16];
    #pragma unroll
    for (int o = 0; o < 16; o++) { acc0[o] = 0.f; acc1[o] = 0.f; }

    const float* cb = cen + (size_t)bz*CIN*HW;

    for (int ci = 0; ci < CIN; ci++) {
        __syncthreads();
        const float* cc = cb + (size_t)ci*HW;
        for (int j = tid; j < 660; j += 256) {
            int r = j / 66, c = j % 66;
            int gy = y0 + r, gx = x0 + c;
            float v = 0.f;
            if ((unsigned)gy < (unsigned)IMGH && (unsigned)gx < (unsigned)IMGW)
                v = __ldg(&cc[gy*IMGW + gx]);
            tile[r][c] = v;
        }
        if (tid < 192) ((float*)wch)[tid] = g_w2p[ci*192 + tid];
        __syncthreads();

        float xv[3][4];
        #pragma unroll
        for (int r = 0; r < 3; r++) {
            float2 a  = *(const float2*)&tile[ty+r][2*tx];
            float2 b2 = *(const float2*)&tile[ty+r][2*tx+2];
            xv[r][0] = a.x; xv[r][1] = a.y; xv[r][2] = b2.x; xv[r][3] = b2.y;
        }
        #pragma unroll
        for (int o = 0; o < 16; o++) {
            const float4* wr = (const float4*)&wch[o][0];
            float4 w0 = wr[0], w1 = wr[1], w2 = wr[2];
            acc0[o] += w0.x*xv[0][0] + w0.y*xv[0][1] + w0.z*xv[0][2]
                     + w0.w*xv[1][0] + w1.x*xv[1][1] + w1.y*xv[1][2]
                     + w1.z*xv[2][0] + w1.w*xv[2][1] + w2.x*xv[2][2];
            acc1[o] += w0.x*xv[0][1] + w0.y*xv[0][2] + w0.z*xv[0][3]
                     + w0.w*xv[1][1] + w1.x*xv[1][2] + w1.y*xv[1][3]
                     + w1.z*xv[2][1] + w1.w*xv[2][2] + w2.x*xv[2][3];
        }
    }

    int gx = x0 + 1 + 2*tx;
    int gy = y0 + 1 + ty;
    float* hp = g_h[1] + (size_t)bz*HID*HW;
    #pragma unroll
    for (int o = 0; o < 16; o++) {
        float bv = bias[o];
        hp[(size_t)o*HW + gy*IMGW + gx]     = acc0[o] + bv;
        hp[(size_t)o*HW + gy*IMGW + gx + 1] = acc1[o] + bv;
    }
}

// ---------------- K3/K4: branch (shift attention) ----------------
// 128 threads/block, 1 pixel/thread. v1,v3 in padded dynamic smem, v2 streamed.
#define PADV 148
__global__ void __launch_bounds__(128)
k_branch(int which,
         const float* __restrict__ w1, const float* __restrict__ w2,
         const float* __restrict__ w3, const float* __restrict__ scale,
         int sidx, int shift, int cbase)
{
    extern __shared__ float sm[];
    float* ws1 = sm;                 // 9*16*16
    float* ws2 = sm + 2304;
    float* ws3 = sm + 4608;
    float* svb = sm + 6912;          // 2 * 128 * PADV

    int tid = threadIdx.x;
    for (int j = tid; j < 2304; j += 128) {
        ws1[j] = w1[j]; ws2[j] = w2[j]; ws3[j] = w3[j];
    }
    __syncthreads();

    int gid = blockIdx.x*128 + tid;
    int bb = gid / HW, p = gid % HW;
    int y = p / IMGW, x = p % IMGW;
    const float* hb = g_h[which] + (size_t)bb*HID*HW;
    float* sv1 = svb + tid*PADV;
    float* sv3 = svb + 128*PADV + tid*PADV;

    float hv[16];

    // phase 1: v1[g], v3[g] -> smem
    for (int g = 0; g < 9; g++) {
        int yy = y + shift*c_dy[g];
        int xx = x + shift*c_dx[g];
        bool inb = ((unsigned)yy < (unsigned)IMGH) && ((unsigned)xx < (unsigned)IMGW);
        float sgn = (g < 8) ? -1.f : 1.f;
        const float* hp = hb + yy*IMGW + xx;
        #pragma unroll
        for (int c = 0; c < 16; c++)
            hv[c] = inb ? sgn*__ldg(&hp[(size_t)c*HW]) : 0.f;

        const float* wgA = ws1 + g*256;
        const float* wgB = ws3 + g*256;
        #pragma unroll
        for (int d4 = 0; d4 < 4; d4++) {
            float tA[4], tB[4];
            #pragma unroll
            for (int dd = 0; dd < 4; dd++) {
                int d = d4*4 + dd;
                const float4* wa = (const float4*)(wgA + d*16);
                const float4* wb = (const float4*)(wgB + d*16);
                float a = 0.f, b = 0.f;
                #pragma unroll
                for (int q4 = 0; q4 < 4; q4++) {
                    float4 va = wa[q4];
                    float4 vb = wb[q4];
                    a += va.x*hv[q4*4] + va.y*hv[q4*4+1] + va.z*hv[q4*4+2] + va.w*hv[q4*4+3];
                    b += vb.x*hv[q4*4] + vb.y*hv[q4*4+1] + vb.z*hv[q4*4+2] + vb.w*hv[q4*4+3];
                }
                tA[dd] = a; tB[dd] = b;
            }
            *(float4*)&sv1[g*16 + d4*4] = make_float4(tA[0],tA[1],tA[2],tA[3]);
            *(float4*)&sv3[g*16 + d4*4] = make_float4(tB[0],tB[1],tB[2],tB[3]);
        }
    }

    float sc = __ldg(&scale[sidx]);
    float* catb = g_cat + (size_t)bb*CCAT*HW + (size_t)cbase*HW + p;

    // phase 2: per-p v2, logits over q, softmax, output
    for (int pp = 0; pp < 9; pp++) {
        int yy = y + shift*c_dy[pp];
        int xx = x + shift*c_dx[pp];
        bool inb = ((unsigned)yy < (unsigned)IMGH) && ((unsigned)xx < (unsigned)IMGW);
        float sgn = (pp < 8) ? -1.f : 1.f;
        const float* hp = hb + yy*IMGW + xx;
        #pragma unroll
        for (int c = 0; c < 16; c++)
            hv[c] = inb ? sgn*__ldg(&hp[(size_t)c*HW]) : 0.f;

        float v2[16];
        const float* wg = ws2 + pp*256;
        #pragma unroll
        for (int d = 0; d < 16; d++) {
            const float4* wr = (const float4*)(wg + d*16);
            float a = 0.f;
            #pragma unroll
            for (int q4 = 0; q4 < 4; q4++) {
                float4 wv = wr[q4];
                a += wv.x*hv[q4*4] + wv.y*hv[q4*4+1] + wv.z*hv[q4*4+2] + wv.w*hv[q4*4+3];
            }
            v2[d] = a;
        }

        float lg[9];
        #pragma unroll
        for (int q = 0; q < 9; q++) {
            const float4* u = (const float4*)&sv1[q*16];
            float4 u0 = u[0], u1 = u[1], u2 = u[2], u3 = u[3];
            float a = u0.x*v2[0]  + u0.y*v2[1]  + u0.z*v2[2]  + u0.w*v2[3]
                    + u1.x*v2[4]  + u1.y*v2[5]  + u1.z*v2[6]  + u1.w*v2[7]
                    + u2.x*v2[8]  + u2.y*v2[9]  + u2.z*v2[10] + u2.w*v2[11]
                    + u3.x*v2[12] + u3.y*v2[13] + u3.z*v2[14] + u3.w*v2[15];
            lg[q] = a * sc;
        }
        float m = lg[0];
        #pragma unroll
        for (int q = 1; q < 9; q++) m = fmaxf(m, lg[q]);
        float s = 0.f;
        #pragma unroll
        for (int q = 0; q < 9; q++) { lg[q] = __expf(lg[q] - m); s += lg[q]; }
        float inv = 1.f / s;

        float oa[16];
        #pragma unroll
        for (int c = 0; c < 16; c++) oa[c] = 0.f;
        #pragma unroll
        for (int q = 0; q < 9; q++) {
            float a = lg[q] * inv;
            const float4* u = (const float4*)&sv3[q*16];
            float4 u0 = u[0], u1 = u[1], u2 = u[2], u3 = u[3];
            oa[0]  += a*u0.x; oa[1]  += a*u0.y; oa[2]  += a*u0.z; oa[3]  += a*u0.w;
            oa[4]  += a*u1.x; oa[5]  += a*u1.y; oa[6]  += a*u1.z; oa[7]  += a*u1.w;
            oa[8]  += a*u2.x; oa[9]  += a*u2.y; oa[10] += a*u2.z; oa[11] += a*u2.w;
            oa[12] += a*u3.x; oa[13] += a*u3.y; oa[14] += a*u3.z; oa[15] += a*u3.w;
        }
        #pragma unroll
        for (int c = 0; c < 16; c++)
            catb[(size_t)(pp*16 + c)*HW] = oa[c];
    }
}

// ---------------- K5: final 1x1 conv 288->128 (+bias) ----------------
__global__ void __launch_bounds__(256)
k_out(const float* __restrict__ wo, const float* __restrict__ bo,
      float* __restrict__ out)
{
    __shared__ float ws[72*132];                 // [i][o] padded row 132
    int tid = threadIdx.x;
    int gid = blockIdx.x*256 + tid;
    int bb = gid / HW, p = gid % HW;
    const float* cp = g_cat + (size_t)bb*CCAT*HW + p;

    float acc[128];
    #pragma unroll
    for (int o = 0; o < 128; o++) acc[o] = 0.f;

    for (int ch = 0; ch < CCAT; ch += 72) {
        __syncthreads();
        for (int j = tid; j < 72*128; j += 256) {
            int i = j % 72, o = j / 72;               // coalesced global read
            ws[i*132 + o] = wo[o*CCAT + ch + i];
        }
        __syncthreads();
        for (int i = 0; i < 72; i++) {
            float v = __ldg(&cp[(size_t)(ch + i)*HW]);
            const float4* wr = (const float4*)&ws[i*132];
            #pragma unroll
            for (int o4 = 0; o4 < 32; o4++) {
                float4 wv = wr[o4];
                acc[o4*4+0] += v*wv.x;
                acc[o4*4+1] += v*wv.y;
                acc[o4*4+2] += v*wv.z;
                acc[o4*4+3] += v*wv.w;
            }
        }
    }
    float* op = out + (size_t)bb*COUT*HW + p;
    #pragma unroll
    for (int o = 0; o < 128; o++)
        op[(size_t)o*HW] = acc[o] + __ldg(&bo[o]);
}

// ---------------- launcher ----------------
extern "C" void kernel_launch(void* const* d_in, const int* in_sizes, int n_in,
                              void* d_out, int out_size)
{
    const float* cen   = (const float*)d_in[0];
    const float* in_w0 = (const float*)d_in[1];
    const float* in_b0 = (const float*)d_in[2];
    const float* in_w1 = (const float*)d_in[3];
    const float* in_b1 = (const float*)d_in[4];
    const float* w1_0  = (const float*)d_in[5];
    const float* w2_0  = (const float*)d_in[6];
    const float* w3_0  = (const float*)d_in[7];
    const float* w1_1  = (const float*)d_in[8];
    const float* w2_1  = (const float*)d_in[9];
    const float* w3_1  = (const float*)d_in[10];
    const float* scale = (const float*)d_in[11];
    const float* out_w = (const float*)d_in[12];
    const float* out_b = (const float*)d_in[13];
    float* out = (float*)d_out;

    size_t br_smem = (size_t)(6912 + 2*128*PADV) * sizeof(float);   // 179200 B
    cudaFuncSetAttribute(k_branch, cudaFuncAttributeMaxDynamicSharedMemorySize,
                         (int)br_smem);

    k_prep<<<(CIN*16*12 + 255)/256, 256>>>(in_w1);
    k_conv1x1<<<HB*HW/256, 256>>>(cen, in_w0, in_b0);
    k_conv3x3<<<dim3(IMGW/64, IMGH/8, HB), dim3(32, 8)>>>(cen, in_b1);
    k_branch<<<HB*HW/128, 128, br_smem>>>(0, w1_0, w2_0, w3_0, scale, 0, 1, 0);
    k_branch<<<HB*HW/128, 128, br_smem>>>(1, w1_1, w2_1, w3_1, scale, 1, 5, 144);
    k_out<<<HB*HW/256, 256>>>(out_w, out_b, out);
}